// round 15
// baseline (speedup 1.0000x reference)
#include <cuda_runtime.h>
#include <math.h>
#include <stdint.h>

#define TT 512
#define BB 128
#define HH 256
#define AA 18
#define BH (BB*HH)
#define NCTA 128

#define OFF_BASE 1179648u
#define OFF_ACT  1245184u
#define OFF_HT   1310720u
#define OFF_CT   1376256u

typedef unsigned long long ull;

static __device__ __align__(16) float g_core[(size_t)TT*BH];  // layer-1 h per step
static __device__ __align__(16) float g_h0buf[2][BH];         // layer-0 h ping-pong (UNMASKED)
static __device__ __align__(16) float g_nd[TT*BB];            // float not-done mask
static __device__ __align__(128) unsigned g_flags[NCTA];      // per-CTA arrival flags
static __device__ int g_mode;

// ---------------- packed f32x2 + sync helpers ----------------
__device__ __forceinline__ ull ffma2(ull a, ull b, ull c){
    ull d;
    asm("fma.rn.f32x2 %0,%1,%2,%3;" : "=l"(d) : "l"(a), "l"(b), "l"(c));
    return d;
}
__device__ __forceinline__ float hsum2(ull v){
    float lo, hi;
    asm("mov.b64 {%0,%1},%2;" : "=f"(lo), "=f"(hi) : "l"(v));
    return lo + hi;
}
__device__ __forceinline__ ull pack2(float lo, float hi){
    ull r;
    asm("mov.b64 %0,{%1,%2};" : "=l"(r) : "f"(lo), "f"(hi));
    return r;
}
__device__ __forceinline__ float sigf(float x){ return 1.0f/(1.0f+__expf(-x)); }
__device__ __forceinline__ float tanhe(float x){ return 1.0f - 2.0f/(__expf(2.0f*x)+1.0f); }

__device__ __forceinline__ unsigned ld_acq(const unsigned* p){
    unsigned v;
    asm volatile("ld.acquire.gpu.u32 %0,[%1];" : "=r"(v) : "l"(p));
    return v;
}
__device__ __forceinline__ void st_rel(unsigned* p, unsigned v){
    asm volatile("st.release.gpu.u32 [%0],%1;" :: "l"(p), "r"(v));
}

// Grid barrier: each CTA releases its own flag; warp 0 of EVERY CTA polls all
// 128 flags directly (4 per lane) — no leader/epoch second hop.
__device__ __forceinline__ void gsync(unsigned target, int bx){
    __syncthreads();
    if (threadIdx.x < 32){
        if (threadIdx.x == 0){ __threadfence(); st_rel(&g_flags[bx], target); }
        unsigned mn;
        do {
            mn = 0xFFFFFFFFu;
#pragma unroll
            for (int i = 0; i < 4; i++){
                unsigned f = ld_acq(&g_flags[threadIdx.x*4 + i]);
                mn = mn < f ? mn : f;
            }
        } while (!__all_sync(0xFFFFFFFFu, mn >= target));
    }
    __syncthreads();
}

// cg (L2-coherent) 16B load / 4B store
__device__ __forceinline__ ulonglong2 ldcg2(const float* p){
    longlong2 t = __ldcg((const longlong2*)p);
    ulonglong2 r; r.x = (ull)t.x; r.y = (ull)t.y;
    return r;
}
__device__ __forceinline__ void stcg1(float* p, float v){ __stcg(p, v); }

// ---- classify 'done' wire dtype; also reset barrier state ----
__global__ void detect_kernel(const unsigned* __restrict__ dw){
    __shared__ int s[5];
    if (threadIdx.x < 5) s[threadIdx.x] = 0;
    if (threadIdx.x < NCTA) g_flags[threadIdx.x] = 0;
    __syncthreads();
    int anynz=0, badf=0, badi=0, badb=0, mix=0;
    for (int i = threadIdx.x; i < 16384; i += 256){
        unsigned w = dw[i];
        if (w) anynz = 1;
        if (w != 0u && w != 0x3F800000u) badf = 1;
        if (w > 1u) badi = 1;
        unsigned h0 = w & 0xFFFFu, h1 = w >> 16;
        if ((h0 && h0 != 0x3F80u) || (h1 && h1 != 0x3F80u)) badb = 1;
        if (w == 0x00003F80u || w == 0x3F803F80u) mix = 1;
    }
    if (anynz) atomicOr(&s[0],1);
    if (badf)  atomicOr(&s[1],1);
    if (badi)  atomicOr(&s[2],1);
    if (badb)  atomicOr(&s[3],1);
    if (mix)   atomicOr(&s[4],1);
    __syncthreads();
    if (threadIdx.x == 0){
        int m;
        if (!s[0]) m = 0;
        else if (!s[3] && s[4]) m = 3;
        else if (!s[1]) m = 2;
        else if (!s[2]) m = 1;
        else m = 0;
        g_mode = m;
    }
}

__global__ void convert_kernel(const void* __restrict__ dptr){
    int i = blockIdx.x*256 + threadIdx.x;
    int m = g_mode; int v;
    if (m == 0)      v = ((const unsigned char*) dptr)[i] != 0;
    else if (m == 1) v = ((const int*)           dptr)[i] != 0;
    else if (m == 2) v = ((const float*)         dptr)[i] != 0.0f;
    else             v = ((const unsigned short*)dptr)[i] != 0;
    g_nd[i] = v ? 0.0f : 1.0f;
}

// no-op: aligns ncu's skip-count so the scan kernel lands in the captured slot
__global__ void dummy_kernel(){}

// Fold-exchange: halve the live accumulator set while butterflying lanes.
__device__ __forceinline__ float foldx(float x, float y, bool hi, int off){
    float mine = hi ? y : x;
    float send = hi ? x : y;
    return mine + __shfl_xor_sync(0xFFFFFFFFu, send, off);
}

__device__ __forceinline__ void loadrow(ulonglong2* A, const float* __restrict__ xin,
                                        const float* __restrict__ hin, int row, int lane){
    const float* xp = xin + row*256 + 4*lane;
    const float* hp = hin + row*256 + 4*lane;
    A[0] = ldcg2(xp);
    A[1] = ldcg2(xp + 128);
    A[2] = ldcg2(hp);
    A[3] = ldcg2(hp + 128);
}

__device__ __forceinline__ void rowdots(const ulonglong2* __restrict__ A, float m,
                                        const ulonglong2 (*__restrict__ W)[4], float* v){
    const ull z = 0ull;
    const ull m2 = pack2(m, m);
    ull h0 = ffma2(A[2].x, m2, z);
    ull h1 = ffma2(A[2].y, m2, z);
    ull h2 = ffma2(A[3].x, m2, z);
    ull h3 = ffma2(A[3].y, m2, z);
#pragma unroll
    for (int ug = 0; ug < 8; ug++){
        ull a;
        a = ffma2(A[0].x, W[ug][0].x, z);
        a = ffma2(A[0].y, W[ug][0].y, a);
        a = ffma2(A[1].x, W[ug][1].x, a);
        a = ffma2(A[1].y, W[ug][1].y, a);
        a = ffma2(h0,     W[ug][2].x, a);
        a = ffma2(h1,     W[ug][2].y, a);
        a = ffma2(h2,     W[ug][3].x, a);
        a = ffma2(h3,     W[ug][3].y, a);
        v[ug] = hsum2(a);
    }
}

// ---------------- one LSTM layer over this warp's 16 rows ----------------
// lane l covers k-quads [4l,4l+4) and [128+4l,...) of the 256-dim vectors.
// Rows processed in software-pipelined pairs; two fold chains interleave.
// hin is the raw (unmasked) recurrent h; mask applied at read.
__device__ __forceinline__ void do_layer(
    const float* __restrict__ ws_l,   // [8][512] : ug = u*4 + gate(i,f,g,o)
    const float* __restrict__ bs_l,   // [8]
    const float* __restrict__ xin,    // [128][256] current input
    const float* __restrict__ hin,    // [128][256] recurrent h
    const float* __restrict__ nd,     // [128]
    int lane, int rowbase,
    float& c_own, float& h_own)
{
    ulonglong2 W[8][4];
#pragma unroll
    for (int ug = 0; ug < 8; ug++){
        const float* wp = ws_l + ug*512 + 4*lane;
        W[ug][0] = *(const ulonglong2*)(wp);
        W[ug][1] = *(const ulonglong2*)(wp + 128);
        W[ug][2] = *(const ulonglong2*)(wp + 256);
        W[ug][3] = *(const ulonglong2*)(wp + 384);
    }
    const int u = lane & 1;
    const bool h16 = (lane & 16) != 0;
    const bool h8  = (lane & 8)  != 0;
    const bool h4  = (lane & 4)  != 0;
    const int  s0  = u << 4;
    const int  ownr = lane >> 1;
    float a_i = 0.0f, a_f = 0.0f, a_g = 0.0f, a_o = 0.0f;

    ulonglong2 A0[4], A1[4], P0[4], P1[4];
    loadrow(A0, xin, hin, rowbase + 0, lane);
    loadrow(A1, xin, hin, rowbase + 1, lane);

#pragma unroll
    for (int rp = 0; rp < 8; rp++){
        if (rp < 7){
            loadrow(P0, xin, hin, rowbase + 2*rp + 2, lane);
            loadrow(P1, xin, hin, rowbase + 2*rp + 3, lane);
        }
        const float m0 = nd[rowbase + 2*rp];
        const float m1 = nd[rowbase + 2*rp + 1];
        float v0[8], v1[8];
        rowdots(A0, m0, W, v0);
        rowdots(A1, m1, W, v1);
        // interleaved fold chains for the two rows
        float u00 = foldx(v0[0], v0[4], h16, 16);
        float u10 = foldx(v1[0], v1[4], h16, 16);
        float u01 = foldx(v0[1], v0[5], h16, 16);
        float u11 = foldx(v1[1], v1[5], h16, 16);
        float u02 = foldx(v0[2], v0[6], h16, 16);
        float u12 = foldx(v1[2], v1[6], h16, 16);
        float u03 = foldx(v0[3], v0[7], h16, 16);
        float u13 = foldx(v1[3], v1[7], h16, 16);
        float p00 = foldx(u00, u02, h8, 8);
        float p10 = foldx(u10, u12, h8, 8);
        float p01 = foldx(u01, u03, h8, 8);
        float p11 = foldx(u11, u13, h8, 8);
        float r0 = foldx(p00, p01, h4, 4);
        float r1 = foldx(p10, p11, h4, 4);
        r0 += __shfl_xor_sync(0xFFFFFFFFu, r0, 2);
        r1 += __shfl_xor_sync(0xFFFFFFFFu, r1, 2);
        r0 += __shfl_xor_sync(0xFFFFFFFFu, r0, 1);
        r1 += __shfl_xor_sync(0xFFFFFFFFu, r1, 1);
        float gi0 = __shfl_sync(0xFFFFFFFFu, r0, s0);
        float gf0 = __shfl_sync(0xFFFFFFFFu, r0, s0 + 4);
        float gg0 = __shfl_sync(0xFFFFFFFFu, r0, s0 + 8);
        float go0 = __shfl_sync(0xFFFFFFFFu, r0, s0 + 12);
        float gi1 = __shfl_sync(0xFFFFFFFFu, r1, s0);
        float gf1 = __shfl_sync(0xFFFFFFFFu, r1, s0 + 4);
        float gg1 = __shfl_sync(0xFFFFFFFFu, r1, s0 + 8);
        float go1 = __shfl_sync(0xFFFFFFFFu, r1, s0 + 12);
        if (ownr == 2*rp)     { a_i = gi0; a_f = gf0; a_g = gg0; a_o = go0; }
        if (ownr == 2*rp + 1) { a_i = gi1; a_f = gf1; a_g = gg1; a_o = go1; }
#pragma unroll
        for (int q = 0; q < 4; q++){ A0[q] = P0[q]; A1[q] = P1[q]; }
    }
    const float m_own = nd[rowbase + ownr];
    const float gi = a_i + bs_l[4*u+0];
    const float gf = a_f + bs_l[4*u+1];
    const float gg = a_g + bs_l[4*u+2];
    const float go = a_o + bs_l[4*u+3];
    const float cn = sigf(gf)*(c_own*m_own) + sigf(gi)*tanhe(gg);
    h_own = sigf(go)*tanhe(cn);
    c_own = cn;
}

__global__ void __launch_bounds__(256,1) scan_kernel(
    const float* __restrict__ x,   const float* __restrict__ h0in,
    const float* __restrict__ c0in,
    const float* __restrict__ wih, const float* __restrict__ whh,
    const float* __restrict__ bih, const float* __restrict__ bhh,
    float* __restrict__ out)
{
    __shared__ __align__(16) float ws[2][8][512];   // [layer][u*4+g][k] x:0..255 h:256..511
    __shared__ float bs[2][8];
    const int tid = threadIdx.x, bx = blockIdx.x;
    const int lane = tid & 31, w = tid >> 5;
    const int rowbase = w * 16;
    const int row_own = rowbase + (lane >> 1);
    const int u_own = lane & 1;
    const int j = bx*2 + u_own;

    for (int i = tid; i < 8192; i += 256){
        int l = i >> 12, rr = i & 4095, ug = rr >> 9, k = rr & 511;
        int uu = ug >> 2, g = ug & 3;
        int row = g*256 + bx*2 + uu;
        float v = (k < 256) ? wih[((l<<10)+row)*256 + k] : whh[((l<<10)+row)*256 + k - 256];
        ws[l][ug][k] = v;
    }
    if (tid < 16){
        int l = tid >> 3, ug = tid & 7, uu = ug >> 2, g = ug & 3;
        int row = g*256 + bx*2 + uu;
        bs[l][ug] = bih[(l<<10)+row] + bhh[(l<<10)+row];
    }
    stcg1(&g_h0buf[0][row_own*256 + j], h0in[row_own*256 + j]);
    float c0own = c0in[row_own*256 + j];
    float c1own = c0in[BH + row_own*256 + j];
    float h0own = 0.0f, h1own = 0.0f;
    gsync(1, bx);

    int pp = 0;
    for (int t = 0; t < TT; t++){
        const float* nd = g_nd + t*BB;
        // ---- layer 0: x(t) + masked h0(t-1) ----
        do_layer(&ws[0][0][0], &bs[0][0],
                 x + (size_t)t*BH, g_h0buf[pp], nd,
                 lane, rowbase, c0own, h0own);
        stcg1(&g_h0buf[pp^1][row_own*256 + j], h0own);
        gsync((unsigned)(t + 2), bx);
        // prefetch x(t+1) into L2 (8 lines per CTA; 1024 chip-wide)
        if (t + 1 < TT && tid < 8){
            const char* nx = (const char*)(x + (size_t)(t+1)*BH) + (size_t)(bx*8 + tid)*128;
            asm volatile("prefetch.global.L2 [%0];" :: "l"(nx));
        }
        // ---- layer 1: h0(t) (unmasked input) + masked h1(t-1) ----
        const float* h1src = t ? (g_core + (size_t)(t-1)*BH) : (h0in + BH);
        do_layer(&ws[1][0][0], &bs[1][0],
                 g_h0buf[pp^1], h1src, nd,
                 lane, rowbase, c1own, h1own);
        stcg1(&g_core[(size_t)t*BH + row_own*256 + j], h1own);
        pp ^= 1;
    }
    out[OFF_HT +      row_own*256 + j] = h0own;
    out[OFF_HT + BH + row_own*256 + j] = h1own;
    out[OFF_CT +      row_own*256 + j] = c0own;
    out[OFF_CT + BH + row_own*256 + j] = c1own;
}

__global__ void __launch_bounds__(256) head_kernel(
    const float* __restrict__ Wp, const float* __restrict__ bp,
    const float* __restrict__ Wb, const float* __restrict__ bb,
    float* __restrict__ out)
{
    __shared__ float sw[19*256];
    for (int i = threadIdx.x; i < 19*256; i += 256)
        sw[i] = (i < 18*256) ? Wp[i] : Wb[i - 18*256];
    __syncthreads();
    int warp = (blockIdx.x*blockDim.x + threadIdx.x) >> 5;
    int lane = threadIdx.x & 31;
    if (warp >= TT*BB) return;
    const float* cr = g_core + (size_t)warp*256;
    float acc[19];
#pragma unroll
    for (int a = 0; a < 19; a++) acc[a] = 0.0f;
#pragma unroll
    for (int k0 = 0; k0 < 8; k0++){
        float v = cr[k0*32 + lane];
#pragma unroll
        for (int a = 0; a < 19; a++) acc[a] += v * sw[a*256 + k0*32 + lane];
    }
#pragma unroll
    for (int a = 0; a < 19; a++)
        for (int o = 16; o > 0; o >>= 1) acc[a] += __shfl_xor_sync(0xFFFFFFFFu, acc[a], o);
    if (lane == 0){
        float best = -3.0e38f; int bi = 0;
        for (int a = 0; a < 18; a++){
            float lg = acc[a] + bp[a];
            out[(size_t)warp*AA + a] = lg;
            if (lg > best){ best = lg; bi = a; }
        }
        out[OFF_BASE + warp] = acc[18] + bb[0];
        out[OFF_ACT  + warp] = (float)bi;
    }
}

extern "C" void kernel_launch(void* const* d_in, const int* in_sizes, int n_in,
                              void* d_out, int out_size){
    const float* x    = (const float*)d_in[0];
    const void*  done = d_in[1];
    const float* h0   = (const float*)d_in[2];
    const float* c0   = (const float*)d_in[3];
    const float* wih  = (const float*)d_in[4];
    const float* whh  = (const float*)d_in[5];
    const float* bih  = (const float*)d_in[6];
    const float* bhh  = (const float*)d_in[7];
    const float* Wp   = (const float*)d_in[8];
    const float* bp   = (const float*)d_in[9];
    const float* Wb   = (const float*)d_in[10];
    const float* bb   = (const float*)d_in[11];
    float* out = (float*)d_out;

    detect_kernel<<<1, 256>>>((const unsigned*)done);
    convert_kernel<<<256, 256>>>(done);
    dummy_kernel<<<1, 32>>>();                 // slot alignment: scan -> ncu capture slot
    scan_kernel<<<NCTA, 256>>>(x, h0, c0, wih, whh, bih, bhh, out);
    head_kernel<<<8192, 256>>>(Wp, bp, Wb, bb, out);
}

// round 16
// speedup vs baseline: 1.2241x; 1.2241x over previous
#include <cuda_runtime.h>
#include <math.h>
#include <stdint.h>

#define TT 512
#define BB 128
#define HH 256
#define AA 18
#define BH (BB*HH)
#define NCTA 128

#define OFF_BASE 1179648u
#define OFF_ACT  1245184u
#define OFF_HT   1310720u
#define OFF_CT   1376256u

typedef unsigned long long ull;

static __device__ __align__(16) float g_core[(size_t)TT*BH];  // layer-1 h per step
static __device__ __align__(16) float g_h0buf[2][BH];         // layer-0 h ping-pong (unmasked)
static __device__ __align__(16) float g_nd[TT*BB];            // float not-done mask
static __device__ __align__(128) unsigned g_flags[NCTA];      // per-CTA arrival flags
static __device__ unsigned g_epoch;
static __device__ int g_mode;

// ---------------- packed f32x2 + sync helpers ----------------
__device__ __forceinline__ ull ffma2(ull a, ull b, ull c){
    ull d;
    asm("fma.rn.f32x2 %0,%1,%2,%3;" : "=l"(d) : "l"(a), "l"(b), "l"(c));
    return d;
}
__device__ __forceinline__ float hsum2(ull v){
    float lo, hi;
    asm("mov.b64 {%0,%1},%2;" : "=f"(lo), "=f"(hi) : "l"(v));
    return lo + hi;
}
__device__ __forceinline__ ull pack2(float lo, float hi){
    ull r;
    asm("mov.b64 %0,{%1,%2};" : "=l"(r) : "f"(lo), "f"(hi));
    return r;
}
__device__ __forceinline__ float sigf(float x){ return 1.0f/(1.0f+__expf(-x)); }
__device__ __forceinline__ float tanhe(float x){ return 1.0f - 2.0f/(__expf(2.0f*x)+1.0f); }

__device__ __forceinline__ unsigned ld_acq(const unsigned* p){
    unsigned v;
    asm volatile("ld.acquire.gpu.u32 %0,[%1];" : "=r"(v) : "l"(p));
    return v;
}
__device__ __forceinline__ void st_rel(unsigned* p, unsigned v){
    asm volatile("st.release.gpu.u32 [%0],%1;" :: "l"(p), "r"(v));
}

// Leader barrier (proven fastest): every CTA releases its own flag; CTA 0's
// warp 0 polls all 128 flags (4 per lane) and releases the epoch; all other
// CTAs poll the single epoch word (same-line reads are merged in L2).
__device__ __forceinline__ void gsync(unsigned target, int bx){
    __syncthreads();
    if (bx == 0){
        if (threadIdx.x < 32){
            __threadfence();
            int lane = threadIdx.x;
            if (lane == 0) st_rel(&g_flags[0], target);
            bool ok;
            do {
                unsigned mn = 0xFFFFFFFFu;
#pragma unroll
                for (int i = 0; i < 4; i++){
                    unsigned f = ld_acq(&g_flags[lane*4 + i]);
                    mn = mn < f ? mn : f;
                }
                ok = __all_sync(0xFFFFFFFFu, mn >= target);
            } while (!ok);
            if (lane == 0) st_rel(&g_epoch, target);
        }
    } else {
        if (threadIdx.x == 0){
            __threadfence();
            st_rel(&g_flags[bx], target);
            while (ld_acq(&g_epoch) < target) {}
        }
    }
    __syncthreads();
}

// cg (L2-coherent) 16B load / 4B store
__device__ __forceinline__ ulonglong2 ldcg2(const float* p){
    longlong2 t = __ldcg((const longlong2*)p);
    ulonglong2 r; r.x = (ull)t.x; r.y = (ull)t.y;
    return r;
}
__device__ __forceinline__ void stcg1(float* p, float v){ __stcg(p, v); }

// ---- classify 'done' wire dtype; also reset barrier state ----
__global__ void detect_kernel(const unsigned* __restrict__ dw){
    __shared__ int s[5];
    if (threadIdx.x < 5) s[threadIdx.x] = 0;
    if (threadIdx.x < NCTA) g_flags[threadIdx.x] = 0;
    __syncthreads();
    int anynz=0, badf=0, badi=0, badb=0, mix=0;
    for (int i = threadIdx.x; i < 16384; i += 256){
        unsigned w = dw[i];
        if (w) anynz = 1;
        if (w != 0u && w != 0x3F800000u) badf = 1;
        if (w > 1u) badi = 1;
        unsigned h0 = w & 0xFFFFu, h1 = w >> 16;
        if ((h0 && h0 != 0x3F80u) || (h1 && h1 != 0x3F80u)) badb = 1;
        if (w == 0x00003F80u || w == 0x3F803F80u) mix = 1;
    }
    if (anynz) atomicOr(&s[0],1);
    if (badf)  atomicOr(&s[1],1);
    if (badi)  atomicOr(&s[2],1);
    if (badb)  atomicOr(&s[3],1);
    if (mix)   atomicOr(&s[4],1);
    __syncthreads();
    if (threadIdx.x == 0){
        int m;
        if (!s[0]) m = 0;
        else if (!s[3] && s[4]) m = 3;
        else if (!s[1]) m = 2;
        else if (!s[2]) m = 1;
        else m = 0;
        g_mode = m; g_epoch = 0;
    }
}

__global__ void convert_kernel(const void* __restrict__ dptr){
    int i = blockIdx.x*256 + threadIdx.x;
    int m = g_mode; int v;
    if (m == 0)      v = ((const unsigned char*) dptr)[i] != 0;
    else if (m == 1) v = ((const int*)           dptr)[i] != 0;
    else if (m == 2) v = ((const float*)         dptr)[i] != 0.0f;
    else             v = ((const unsigned short*)dptr)[i] != 0;
    g_nd[i] = v ? 0.0f : 1.0f;
}

// no-op: aligns ncu's skip-count so the scan kernel lands in the captured slot
__global__ void dummy_kernel(){}

// Fold-exchange: halve the live accumulator set while butterflying lanes.
__device__ __forceinline__ float foldx(float x, float y, bool hi, int off){
    float mine = hi ? y : x;
    float send = hi ? x : y;
    return mine + __shfl_xor_sync(0xFFFFFFFFu, send, off);
}

__device__ __forceinline__ void loadrow(ulonglong2* A, const float* __restrict__ xin,
                                        const float* __restrict__ hin, int row, int lane){
    const float* xp = xin + row*256 + 4*lane;
    const float* hp = hin + row*256 + 4*lane;
    A[0] = ldcg2(xp);
    A[1] = ldcg2(xp + 128);
    A[2] = ldcg2(hp);
    A[3] = ldcg2(hp + 128);
}

__device__ __forceinline__ void rowdots(const ulonglong2* __restrict__ A, float m,
                                        const ulonglong2 (*__restrict__ W)[4], float* v){
    const ull z = 0ull;
    const ull m2 = pack2(m, m);
    ull h0 = ffma2(A[2].x, m2, z);
    ull h1 = ffma2(A[2].y, m2, z);
    ull h2 = ffma2(A[3].x, m2, z);
    ull h3 = ffma2(A[3].y, m2, z);
#pragma unroll
    for (int ug = 0; ug < 8; ug++){
        ull a;
        a = ffma2(A[0].x, W[ug][0].x, z);
        a = ffma2(A[0].y, W[ug][0].y, a);
        a = ffma2(A[1].x, W[ug][1].x, a);
        a = ffma2(A[1].y, W[ug][1].y, a);
        a = ffma2(h0,     W[ug][2].x, a);
        a = ffma2(h1,     W[ug][2].y, a);
        a = ffma2(h2,     W[ug][3].x, a);
        a = ffma2(h3,     W[ug][3].y, a);
        v[ug] = hsum2(a);
    }
}

// ---------------- one LSTM layer over this warp's 16 rows ----------------
// lane l covers k-quads [4l,4l+4) and [128+4l,...) of the 256-dim vectors.
// Rows in interleaved pairs (2 independent fold chains) WITHOUT prefetch
// buffers: keeps register demand ~195 (no spills at the 255 cap).
__device__ __forceinline__ void do_layer(
    const float* __restrict__ ws_l,   // [8][512] : ug = u*4 + gate(i,f,g,o)
    const float* __restrict__ bs_l,   // [8]
    const float* __restrict__ xin,    // [128][256] current input
    const float* __restrict__ hin,    // [128][256] recurrent h (masked at read)
    const float* __restrict__ nd,     // [128]
    int lane, int rowbase,
    float& c_own, float& h_own)
{
    ulonglong2 W[8][4];
#pragma unroll
    for (int ug = 0; ug < 8; ug++){
        const float* wp = ws_l + ug*512 + 4*lane;
        W[ug][0] = *(const ulonglong2*)(wp);
        W[ug][1] = *(const ulonglong2*)(wp + 128);
        W[ug][2] = *(const ulonglong2*)(wp + 256);
        W[ug][3] = *(const ulonglong2*)(wp + 384);
    }
    const int u = lane & 1;
    const bool h16 = (lane & 16) != 0;
    const bool h8  = (lane & 8)  != 0;
    const bool h4  = (lane & 4)  != 0;
    const int  s0  = u << 4;
    const int  ownr = lane >> 1;
    float a_i = 0.0f, a_f = 0.0f, a_g = 0.0f, a_o = 0.0f;

#pragma unroll
    for (int rp = 0; rp < 8; rp++){
        ulonglong2 A0[4], A1[4];
        loadrow(A0, xin, hin, rowbase + 2*rp,     lane);
        loadrow(A1, xin, hin, rowbase + 2*rp + 1, lane);
        const float m0 = nd[rowbase + 2*rp];
        const float m1 = nd[rowbase + 2*rp + 1];
        float v0[8], v1[8];
        rowdots(A0, m0, W, v0);
        rowdots(A1, m1, W, v1);
        // interleaved fold chains for the two rows
        float u00 = foldx(v0[0], v0[4], h16, 16);
        float u10 = foldx(v1[0], v1[4], h16, 16);
        float u01 = foldx(v0[1], v0[5], h16, 16);
        float u11 = foldx(v1[1], v1[5], h16, 16);
        float u02 = foldx(v0[2], v0[6], h16, 16);
        float u12 = foldx(v1[2], v1[6], h16, 16);
        float u03 = foldx(v0[3], v0[7], h16, 16);
        float u13 = foldx(v1[3], v1[7], h16, 16);
        float p00 = foldx(u00, u02, h8, 8);
        float p10 = foldx(u10, u12, h8, 8);
        float p01 = foldx(u01, u03, h8, 8);
        float p11 = foldx(u11, u13, h8, 8);
        float r0 = foldx(p00, p01, h4, 4);
        float r1 = foldx(p10, p11, h4, 4);
        r0 += __shfl_xor_sync(0xFFFFFFFFu, r0, 2);
        r1 += __shfl_xor_sync(0xFFFFFFFFu, r1, 2);
        r0 += __shfl_xor_sync(0xFFFFFFFFu, r0, 1);
        r1 += __shfl_xor_sync(0xFFFFFFFFu, r1, 1);
        float gi0 = __shfl_sync(0xFFFFFFFFu, r0, s0);
        float gf0 = __shfl_sync(0xFFFFFFFFu, r0, s0 + 4);
        float gg0 = __shfl_sync(0xFFFFFFFFu, r0, s0 + 8);
        float go0 = __shfl_sync(0xFFFFFFFFu, r0, s0 + 12);
        float gi1 = __shfl_sync(0xFFFFFFFFu, r1, s0);
        float gf1 = __shfl_sync(0xFFFFFFFFu, r1, s0 + 4);
        float gg1 = __shfl_sync(0xFFFFFFFFu, r1, s0 + 8);
        float go1 = __shfl_sync(0xFFFFFFFFu, r1, s0 + 12);
        if (ownr == 2*rp)     { a_i = gi0; a_f = gf0; a_g = gg0; a_o = go0; }
        if (ownr == 2*rp + 1) { a_i = gi1; a_f = gf1; a_g = gg1; a_o = go1; }
    }
    const float m_own = nd[rowbase + ownr];
    const float gi = a_i + bs_l[4*u+0];
    const float gf = a_f + bs_l[4*u+1];
    const float gg = a_g + bs_l[4*u+2];
    const float go = a_o + bs_l[4*u+3];
    const float cn = sigf(gf)*(c_own*m_own) + sigf(gi)*tanhe(gg);
    h_own = sigf(go)*tanhe(cn);
    c_own = cn;
}

__global__ void __launch_bounds__(256,1) scan_kernel(
    const float* __restrict__ x,   const float* __restrict__ h0in,
    const float* __restrict__ c0in,
    const float* __restrict__ wih, const float* __restrict__ whh,
    const float* __restrict__ bih, const float* __restrict__ bhh,
    float* __restrict__ out)
{
    __shared__ __align__(16) float ws[2][8][512];   // [layer][u*4+g][k] x:0..255 h:256..511
    __shared__ float bs[2][8];
    const int tid = threadIdx.x, bx = blockIdx.x;
    const int lane = tid & 31, w = tid >> 5;
    const int rowbase = w * 16;
    const int row_own = rowbase + (lane >> 1);
    const int u_own = lane & 1;
    const int j = bx*2 + u_own;

    for (int i = tid; i < 8192; i += 256){
        int l = i >> 12, rr = i & 4095, ug = rr >> 9, k = rr & 511;
        int uu = ug >> 2, g = ug & 3;
        int row = g*256 + bx*2 + uu;
        float v = (k < 256) ? wih[((l<<10)+row)*256 + k] : whh[((l<<10)+row)*256 + k - 256];
        ws[l][ug][k] = v;
    }
    if (tid < 16){
        int l = tid >> 3, ug = tid & 7, uu = ug >> 2, g = ug & 3;
        int row = g*256 + bx*2 + uu;
        bs[l][ug] = bih[(l<<10)+row] + bhh[(l<<10)+row];
    }
    stcg1(&g_h0buf[0][row_own*256 + j], h0in[row_own*256 + j]);
    float c0own = c0in[row_own*256 + j];
    float c1own = c0in[BH + row_own*256 + j];
    float h0own = 0.0f, h1own = 0.0f;
    gsync(1, bx);

    int pp = 0;
    for (int t = 0; t < TT; t++){
        const float* nd = g_nd + t*BB;
        // ---- layer 0: x(t) + masked h0(t-1) ----
        do_layer(&ws[0][0][0], &bs[0][0],
                 x + (size_t)t*BH, g_h0buf[pp], nd,
                 lane, rowbase, c0own, h0own);
        stcg1(&g_h0buf[pp^1][row_own*256 + j], h0own);
        gsync((unsigned)(t + 2), bx);
        // prefetch x(t+1) into L2 (8 lines per CTA; 1024 chip-wide)
        if (t + 1 < TT && tid < 8){
            const char* nx = (const char*)(x + (size_t)(t+1)*BH) + (size_t)(bx*8 + tid)*128;
            asm volatile("prefetch.global.L2 [%0];" :: "l"(nx));
        }
        // ---- layer 1: h0(t) (unmasked input) + masked h1(t-1) ----
        const float* h1src = t ? (g_core + (size_t)(t-1)*BH) : (h0in + BH);
        do_layer(&ws[1][0][0], &bs[1][0],
                 g_h0buf[pp^1], h1src, nd,
                 lane, rowbase, c1own, h1own);
        stcg1(&g_core[(size_t)t*BH + row_own*256 + j], h1own);
        pp ^= 1;
    }
    out[OFF_HT +      row_own*256 + j] = h0own;
    out[OFF_HT + BH + row_own*256 + j] = h1own;
    out[OFF_CT +      row_own*256 + j] = c0own;
    out[OFF_CT + BH + row_own*256 + j] = c1own;
}

__global__ void __launch_bounds__(256) head_kernel(
    const float* __restrict__ Wp, const float* __restrict__ bp,
    const float* __restrict__ Wb, const float* __restrict__ bb,
    float* __restrict__ out)
{
    __shared__ float sw[19*256];
    for (int i = threadIdx.x; i < 19*256; i += 256)
        sw[i] = (i < 18*256) ? Wp[i] : Wb[i - 18*256];
    __syncthreads();
    int warp = (blockIdx.x*blockDim.x + threadIdx.x) >> 5;
    int lane = threadIdx.x & 31;
    if (warp >= TT*BB) return;
    const float* cr = g_core + (size_t)warp*256;
    float acc[19];
#pragma unroll
    for (int a = 0; a < 19; a++) acc[a] = 0.0f;
#pragma unroll
    for (int k0 = 0; k0 < 8; k0++){
        float v = cr[k0*32 + lane];
#pragma unroll
        for (int a = 0; a < 19; a++) acc[a] += v * sw[a*256 + k0*32 + lane];
    }
#pragma unroll
    for (int a = 0; a < 19; a++)
        for (int o = 16; o > 0; o >>= 1) acc[a] += __shfl_xor_sync(0xFFFFFFFFu, acc[a], o);
    if (lane == 0){
        float best = -3.0e38f; int bi = 0;
        for (int a = 0; a < 18; a++){
            float lg = acc[a] + bp[a];
            out[(size_t)warp*AA + a] = lg;
            if (lg > best){ best = lg; bi = a; }
        }
        out[OFF_BASE + warp] = acc[18] + bb[0];
        out[OFF_ACT  + warp] = (float)bi;
    }
}

extern "C" void kernel_launch(void* const* d_in, const int* in_sizes, int n_in,
                              void* d_out, int out_size){
    const float* x    = (const float*)d_in[0];
    const void*  done = d_in[1];
    const float* h0   = (const float*)d_in[2];
    const float* c0   = (const float*)d_in[3];
    const float* wih  = (const float*)d_in[4];
    const float* whh  = (const float*)d_in[5];
    const float* bih  = (const float*)d_in[6];
    const float* bhh  = (const float*)d_in[7];
    const float* Wp   = (const float*)d_in[8];
    const float* bp   = (const float*)d_in[9];
    const float* Wb   = (const float*)d_in[10];
    const float* bb   = (const float*)d_in[11];
    float* out = (float*)d_out;

    detect_kernel<<<1, 256>>>((const unsigned*)done);
    convert_kernel<<<256, 256>>>(done);
    dummy_kernel<<<1, 32>>>();                 // slot alignment: scan -> ncu capture slot
    scan_kernel<<<NCTA, 256>>>(x, h0, c0, wih, whh, bih, bhh, out);
    head_kernel<<<8192, 256>>>(Wp, bp, Wb, bb, out);
}

// round 17
// speedup vs baseline: 1.4844x; 1.2126x over previous
#include <cuda_runtime.h>
#include <math.h>
#include <stdint.h>

#define TT 512
#define BB 128
#define HH 256
#define AA 18
#define BH (BB*HH)
#define NCTA 128

#define OFF_BASE 1179648u
#define OFF_ACT  1245184u
#define OFF_HT   1310720u
#define OFF_CT   1376256u

typedef unsigned long long ull;

static __device__ __align__(16) float g_core[(size_t)TT*BH];  // layer-1 h per step
static __device__ __align__(16) float g_h0buf[2][BH];         // layer-0 h ping-pong (unmasked)
static __device__ __align__(16) float g_nd[TT*BB];            // float not-done mask
static __device__ __align__(128) unsigned g_flags[NCTA];      // per-CTA arrival flags
static __device__ unsigned g_epoch;
static __device__ int g_mode;

// ---------------- packed f32x2 + sync helpers ----------------
__device__ __forceinline__ ull ffma2(ull a, ull b, ull c){
    ull d;
    asm("fma.rn.f32x2 %0,%1,%2,%3;" : "=l"(d) : "l"(a), "l"(b), "l"(c));
    return d;
}
__device__ __forceinline__ float hsum2(ull v){
    float lo, hi;
    asm("mov.b64 {%0,%1},%2;" : "=f"(lo), "=f"(hi) : "l"(v));
    return lo + hi;
}
__device__ __forceinline__ ull pack2(float lo, float hi){
    ull r;
    asm("mov.b64 %0,{%1,%2};" : "=l"(r) : "f"(lo), "f"(hi));
    return r;
}
__device__ __forceinline__ float sigf(float x){ return 1.0f/(1.0f+__expf(-x)); }
__device__ __forceinline__ float tanhe(float x){ return 1.0f - 2.0f/(__expf(2.0f*x)+1.0f); }

__device__ __forceinline__ unsigned ld_acq(const unsigned* p){
    unsigned v;
    asm volatile("ld.acquire.gpu.u32 %0,[%1];" : "=r"(v) : "l"(p));
    return v;
}
__device__ __forceinline__ void st_rel(unsigned* p, unsigned v){
    asm volatile("st.release.gpu.u32 [%0],%1;" :: "l"(p), "r"(v));
}
__device__ __forceinline__ void stcg1(float* p, float v){ __stcg(p, v); }

// cp.async 16B, L1-bypassing (L2-coherent with peer st.cg writes)
__device__ __forceinline__ void cpa16(float* s, const float* g){
    unsigned sa = (unsigned)__cvta_generic_to_shared(s);
    asm volatile("cp.async.cg.shared.global [%0], [%1], 16;" :: "r"(sa), "l"(g));
}

// Leader barrier (proven fastest): every CTA releases its own flag; CTA 0's
// warp 0 polls all 128 flags (4 per lane) and releases the epoch; all other
// CTAs poll the single epoch word (same-line reads are merged in L2).
__device__ __forceinline__ void gsync(unsigned target, int bx){
    __syncthreads();
    if (bx == 0){
        if (threadIdx.x < 32){
            __threadfence();
            int lane = threadIdx.x;
            if (lane == 0) st_rel(&g_flags[0], target);
            bool ok;
            do {
                unsigned mn = 0xFFFFFFFFu;
#pragma unroll
                for (int i = 0; i < 4; i++){
                    unsigned f = ld_acq(&g_flags[lane*4 + i]);
                    mn = mn < f ? mn : f;
                }
                ok = __all_sync(0xFFFFFFFFu, mn >= target);
            } while (!ok);
            if (lane == 0) st_rel(&g_epoch, target);
        }
    } else {
        if (threadIdx.x == 0){
            __threadfence();
            st_rel(&g_flags[bx], target);
            while (ld_acq(&g_epoch) < target) {}
        }
    }
    __syncthreads();
}

// ---- classify 'done' wire dtype; also reset barrier state ----
__global__ void detect_kernel(const unsigned* __restrict__ dw){
    __shared__ int s[5];
    if (threadIdx.x < 5) s[threadIdx.x] = 0;
    if (threadIdx.x < NCTA) g_flags[threadIdx.x] = 0;
    __syncthreads();
    int anynz=0, badf=0, badi=0, badb=0, mix=0;
    for (int i = threadIdx.x; i < 16384; i += 256){
        unsigned w = dw[i];
        if (w) anynz = 1;
        if (w != 0u && w != 0x3F800000u) badf = 1;
        if (w > 1u) badi = 1;
        unsigned h0 = w & 0xFFFFu, h1 = w >> 16;
        if ((h0 && h0 != 0x3F80u) || (h1 && h1 != 0x3F80u)) badb = 1;
        if (w == 0x00003F80u || w == 0x3F803F80u) mix = 1;
    }
    if (anynz) atomicOr(&s[0],1);
    if (badf)  atomicOr(&s[1],1);
    if (badi)  atomicOr(&s[2],1);
    if (badb)  atomicOr(&s[3],1);
    if (mix)   atomicOr(&s[4],1);
    __syncthreads();
    if (threadIdx.x == 0){
        int m;
        if (!s[0]) m = 0;
        else if (!s[3] && s[4]) m = 3;
        else if (!s[1]) m = 2;
        else if (!s[2]) m = 1;
        else m = 0;
        g_mode = m; g_epoch = 0;
    }
}

__global__ void convert_kernel(const void* __restrict__ dptr){
    int i = blockIdx.x*256 + threadIdx.x;
    int m = g_mode; int v;
    if (m == 0)      v = ((const unsigned char*) dptr)[i] != 0;
    else if (m == 1) v = ((const int*)           dptr)[i] != 0;
    else if (m == 2) v = ((const float*)         dptr)[i] != 0.0f;
    else             v = ((const unsigned short*)dptr)[i] != 0;
    g_nd[i] = v ? 0.0f : 1.0f;
}

// no-op: aligns ncu's skip-count so the scan kernel lands in the captured slot
__global__ void dummy_kernel(){}

// Fold-exchange: halve the live accumulator set while butterflying lanes.
__device__ __forceinline__ float foldx(float x, float y, bool hi, int off){
    float mine = hi ? y : x;
    float send = hi ? x : y;
    return mine + __shfl_xor_sync(0xFFFFFFFFu, send, off);
}

// Issue cp.async for one row pair into stage `st` of this warp's ring.
// Each lane copies exactly the 16B segments it will later read.
__device__ __forceinline__ void issue_pair(float* abw, int st,
    const float* __restrict__ xin, const float* __restrict__ hin,
    int row0, int lane){
#pragma unroll
    for (int r = 0; r < 2; r++){
        const float* xg = xin + (row0 + r)*256 + 4*lane;
        const float* hg = hin + (row0 + r)*256 + 4*lane;
        float* sb = abw + (st*2 + r)*512 + 4*lane;
        cpa16(sb,       xg);
        cpa16(sb + 128, xg + 128);
        cpa16(sb + 256, hg);
        cpa16(sb + 384, hg + 128);
    }
    asm volatile("cp.async.commit_group;" ::: "memory");
}

// row dots from a staged smem row (pointer already +4*lane)
__device__ __forceinline__ void rowdots_s(const float* __restrict__ sb, float m,
                                          const ulonglong2 (*__restrict__ W)[4], float* v){
    const ull z = 0ull;
    ulonglong2 X0 = *(const ulonglong2*)(sb);
    ulonglong2 X1 = *(const ulonglong2*)(sb + 128);
    ulonglong2 H0 = *(const ulonglong2*)(sb + 256);
    ulonglong2 H1 = *(const ulonglong2*)(sb + 384);
    const ull m2 = pack2(m, m);
    ull h0 = ffma2(H0.x, m2, z);
    ull h1 = ffma2(H0.y, m2, z);
    ull h2 = ffma2(H1.x, m2, z);
    ull h3 = ffma2(H1.y, m2, z);
#pragma unroll
    for (int ug = 0; ug < 8; ug++){
        ull a;
        a = ffma2(X0.x, W[ug][0].x, z);
        a = ffma2(X0.y, W[ug][0].y, a);
        a = ffma2(X1.x, W[ug][1].x, a);
        a = ffma2(X1.y, W[ug][1].y, a);
        a = ffma2(h0,   W[ug][2].x, a);
        a = ffma2(h1,   W[ug][2].y, a);
        a = ffma2(h2,   W[ug][3].x, a);
        a = ffma2(h3,   W[ug][3].y, a);
        v[ug] = hsum2(a);
    }
}

// ---------------- one LSTM layer over this warp's 16 rows ----------------
// Activations staged via a 3-deep cp.async ring (2 pairs of lookahead).
__device__ __forceinline__ void do_layer(
    const float* __restrict__ ws_l,   // [8][512] : ug = u*4 + gate(i,f,g,o)
    const float* __restrict__ bs_l,   // [8]
    const float* __restrict__ xin,    // [128][256] current input
    const float* __restrict__ hin,    // [128][256] recurrent h (masked at read)
    const float* __restrict__ nd,     // [128]
    float* abw,                       // this warp's [3][2][512] staging ring
    int lane, int rowbase,
    float& c_own, float& h_own)
{
    ulonglong2 W[8][4];
#pragma unroll
    for (int ug = 0; ug < 8; ug++){
        const float* wp = ws_l + ug*512 + 4*lane;
        W[ug][0] = *(const ulonglong2*)(wp);
        W[ug][1] = *(const ulonglong2*)(wp + 128);
        W[ug][2] = *(const ulonglong2*)(wp + 256);
        W[ug][3] = *(const ulonglong2*)(wp + 384);
    }
    const int u = lane & 1;
    const bool h16 = (lane & 16) != 0;
    const bool h8  = (lane & 8)  != 0;
    const bool h4  = (lane & 4)  != 0;
    const int  s0  = u << 4;
    const int  ownr = lane >> 1;
    float a_i = 0.0f, a_f = 0.0f, a_g = 0.0f, a_o = 0.0f;

    issue_pair(abw, 0, xin, hin, rowbase + 0, lane);
    issue_pair(abw, 1, xin, hin, rowbase + 2, lane);

#pragma unroll
    for (int rp = 0; rp < 8; rp++){
        if (rp < 6) issue_pair(abw, (rp + 2) % 3, xin, hin, rowbase + 2*rp + 4, lane);
        if (rp < 6)       asm volatile("cp.async.wait_group 2;" ::: "memory");
        else if (rp == 6) asm volatile("cp.async.wait_group 1;" ::: "memory");
        else              asm volatile("cp.async.wait_group 0;" ::: "memory");

        const float* sb0 = abw + ((rp % 3)*2 + 0)*512 + 4*lane;
        const float* sb1 = abw + ((rp % 3)*2 + 1)*512 + 4*lane;
        const float m0 = nd[rowbase + 2*rp];
        const float m1 = nd[rowbase + 2*rp + 1];
        float v0[8], v1[8];
        rowdots_s(sb0, m0, W, v0);
        rowdots_s(sb1, m1, W, v1);
        // interleaved fold chains for the two rows
        float u00 = foldx(v0[0], v0[4], h16, 16);
        float u10 = foldx(v1[0], v1[4], h16, 16);
        float u01 = foldx(v0[1], v0[5], h16, 16);
        float u11 = foldx(v1[1], v1[5], h16, 16);
        float u02 = foldx(v0[2], v0[6], h16, 16);
        float u12 = foldx(v1[2], v1[6], h16, 16);
        float u03 = foldx(v0[3], v0[7], h16, 16);
        float u13 = foldx(v1[3], v1[7], h16, 16);
        float p00 = foldx(u00, u02, h8, 8);
        float p10 = foldx(u10, u12, h8, 8);
        float p01 = foldx(u01, u03, h8, 8);
        float p11 = foldx(u11, u13, h8, 8);
        float r0 = foldx(p00, p01, h4, 4);
        float r1 = foldx(p10, p11, h4, 4);
        r0 += __shfl_xor_sync(0xFFFFFFFFu, r0, 2);
        r1 += __shfl_xor_sync(0xFFFFFFFFu, r1, 2);
        r0 += __shfl_xor_sync(0xFFFFFFFFu, r0, 1);
        r1 += __shfl_xor_sync(0xFFFFFFFFu, r1, 1);
        float gi0 = __shfl_sync(0xFFFFFFFFu, r0, s0);
        float gf0 = __shfl_sync(0xFFFFFFFFu, r0, s0 + 4);
        float gg0 = __shfl_sync(0xFFFFFFFFu, r0, s0 + 8);
        float go0 = __shfl_sync(0xFFFFFFFFu, r0, s0 + 12);
        float gi1 = __shfl_sync(0xFFFFFFFFu, r1, s0);
        float gf1 = __shfl_sync(0xFFFFFFFFu, r1, s0 + 4);
        float gg1 = __shfl_sync(0xFFFFFFFFu, r1, s0 + 8);
        float go1 = __shfl_sync(0xFFFFFFFFu, r1, s0 + 12);
        if (ownr == 2*rp)     { a_i = gi0; a_f = gf0; a_g = gg0; a_o = go0; }
        if (ownr == 2*rp + 1) { a_i = gi1; a_f = gf1; a_g = gg1; a_o = go1; }
    }
    const float m_own = nd[rowbase + ownr];
    const float gi = a_i + bs_l[4*u+0];
    const float gf = a_f + bs_l[4*u+1];
    const float gg = a_g + bs_l[4*u+2];
    const float go = a_o + bs_l[4*u+3];
    const float cn = sigf(gf)*(c_own*m_own) + sigf(gi)*tanhe(gg);
    h_own = sigf(go)*tanhe(cn);
    c_own = cn;
}

// dynamic smem: ws 8192 floats | bs 16 | (pad to 8224) | abuf 8 warps x 3072
#define SM_WS   0
#define SM_BS   8192
#define SM_ABUF 8224
#define SM_FLOATS (SM_ABUF + 8*3072)   // 32800 floats = 131200 B

__global__ void __launch_bounds__(256,1) scan_kernel(
    const float* __restrict__ x,   const float* __restrict__ h0in,
    const float* __restrict__ c0in,
    const float* __restrict__ wih, const float* __restrict__ whh,
    const float* __restrict__ bih, const float* __restrict__ bhh,
    float* __restrict__ out)
{
    extern __shared__ __align__(16) float sm[];
    float* ws = sm + SM_WS;      // [2][8][512]
    float* bs = sm + SM_BS;      // [2][8]
    const int tid = threadIdx.x, bx = blockIdx.x;
    const int lane = tid & 31, w = tid >> 5;
    float* abw = sm + SM_ABUF + w*3072;
    const int rowbase = w * 16;
    const int row_own = rowbase + (lane >> 1);
    const int u_own = lane & 1;
    const int j = bx*2 + u_own;

    for (int i = tid; i < 8192; i += 256){
        int l = i >> 12, rr = i & 4095, ug = rr >> 9, k = rr & 511;
        int uu = ug >> 2, g = ug & 3;
        int row = g*256 + bx*2 + uu;
        float v = (k < 256) ? wih[((l<<10)+row)*256 + k] : whh[((l<<10)+row)*256 + k - 256];
        ws[(l*8 + ug)*512 + k] = v;
    }
    if (tid < 16){
        int l = tid >> 3, ug = tid & 7, uu = ug >> 2, g = ug & 3;
        int row = g*256 + bx*2 + uu;
        bs[l*8 + ug] = bih[(l<<10)+row] + bhh[(l<<10)+row];
    }
    stcg1(&g_h0buf[0][row_own*256 + j], h0in[row_own*256 + j]);
    float c0own = c0in[row_own*256 + j];
    float c1own = c0in[BH + row_own*256 + j];
    float h0own = 0.0f, h1own = 0.0f;
    gsync(1, bx);

    int pp = 0;
    for (int t = 0; t < TT; t++){
        const float* nd = g_nd + t*BB;
        // ---- layer 0: x(t) + masked h0(t-1) ----
        do_layer(ws, bs,
                 x + (size_t)t*BH, g_h0buf[pp], nd,
                 abw, lane, rowbase, c0own, h0own);
        stcg1(&g_h0buf[pp^1][row_own*256 + j], h0own);
        gsync((unsigned)(t + 2), bx);
        // prefetch x(t+1) into L2 (8 lines per CTA; 1024 chip-wide)
        if (t + 1 < TT && tid < 8){
            const char* nx = (const char*)(x + (size_t)(t+1)*BH) + (size_t)(bx*8 + tid)*128;
            asm volatile("prefetch.global.L2 [%0];" :: "l"(nx));
        }
        // ---- layer 1: h0(t) (unmasked input) + masked h1(t-1) ----
        const float* h1src = t ? (g_core + (size_t)(t-1)*BH) : (h0in + BH);
        do_layer(ws + 8*512, bs + 8,
                 g_h0buf[pp^1], h1src, nd,
                 abw, lane, rowbase, c1own, h1own);
        stcg1(&g_core[(size_t)t*BH + row_own*256 + j], h1own);
        pp ^= 1;
    }
    out[OFF_HT +      row_own*256 + j] = h0own;
    out[OFF_HT + BH + row_own*256 + j] = h1own;
    out[OFF_CT +      row_own*256 + j] = c0own;
    out[OFF_CT + BH + row_own*256 + j] = c1own;
}

__global__ void __launch_bounds__(256) head_kernel(
    const float* __restrict__ Wp, const float* __restrict__ bp,
    const float* __restrict__ Wb, const float* __restrict__ bb,
    float* __restrict__ out)
{
    __shared__ float sw[19*256];
    for (int i = threadIdx.x; i < 19*256; i += 256)
        sw[i] = (i < 18*256) ? Wp[i] : Wb[i - 18*256];
    __syncthreads();
    int warp = (blockIdx.x*blockDim.x + threadIdx.x) >> 5;
    int lane = threadIdx.x & 31;
    if (warp >= TT*BB) return;
    const float* cr = g_core + (size_t)warp*256;
    float acc[19];
#pragma unroll
    for (int a = 0; a < 19; a++) acc[a] = 0.0f;
#pragma unroll
    for (int k0 = 0; k0 < 8; k0++){
        float v = cr[k0*32 + lane];
#pragma unroll
        for (int a = 0; a < 19; a++) acc[a] += v * sw[a*256 + k0*32 + lane];
    }
#pragma unroll
    for (int a = 0; a < 19; a++)
        for (int o = 16; o > 0; o >>= 1) acc[a] += __shfl_xor_sync(0xFFFFFFFFu, acc[a], o);
    if (lane == 0){
        float best = -3.0e38f; int bi = 0;
        for (int a = 0; a < 18; a++){
            float lg = acc[a] + bp[a];
            out[(size_t)warp*AA + a] = lg;
            if (lg > best){ best = lg; bi = a; }
        }
        out[OFF_BASE + warp] = acc[18] + bb[0];
        out[OFF_ACT  + warp] = (float)bi;
    }
}

extern "C" void kernel_launch(void* const* d_in, const int* in_sizes, int n_in,
                              void* d_out, int out_size){
    const float* x    = (const float*)d_in[0];
    const void*  done = d_in[1];
    const float* h0   = (const float*)d_in[2];
    const float* c0   = (const float*)d_in[3];
    const float* wih  = (const float*)d_in[4];
    const float* whh  = (const float*)d_in[5];
    const float* bih  = (const float*)d_in[6];
    const float* bhh  = (const float*)d_in[7];
    const float* Wp   = (const float*)d_in[8];
    const float* bp   = (const float*)d_in[9];
    const float* Wb   = (const float*)d_in[10];
    const float* bb   = (const float*)d_in[11];
    float* out = (float*)d_out;

    const int SMEM_BYTES = SM_FLOATS * 4;   // 131200
    cudaFuncSetAttribute(scan_kernel, cudaFuncAttributeMaxDynamicSharedMemorySize, SMEM_BYTES);

    detect_kernel<<<1, 256>>>((const unsigned*)done);
    convert_kernel<<<256, 256>>>(done);
    dummy_kernel<<<1, 32>>>();                 // slot alignment: scan -> ncu capture slot
    scan_kernel<<<NCTA, 256, SMEM_BYTES>>>(x, h0, c0, wih, whh, bih, bhh, out);
    head_kernel<<<8192, 256>>>(Wp, bp, Wb, bb, out);
}